// round 9
// baseline (speedup 1.0000x reference)
#include <cuda_runtime.h>

#define T_STEPS 512
#define BATCH   256
#define HID     64
#define DIN     300
#define G4      256
#define MROWS   (T_STEPS * BATCH)

typedef unsigned long long ull;

// ---- scratch (allocation-free: device globals) ----
__device__ float g_xp [(size_t)MROWS * G4];
__device__ float g_hsA[(size_t)MROWS * HID];
__device__ float g_hsB[(size_t)MROWS * HID];

#define FFMA2(acc, a, b) \
    asm("fma.rn.f32x2 %0, %1, %2, %0;" : "+l"(acc) : "l"(a), "l"(b))

__device__ __forceinline__ float2 unpk(ull v) {
    unsigned lo, hi;
    asm("mov.b64 {%0, %1}, %2;" : "=r"(lo), "=r"(hi) : "l"(v));
    return make_float2(__uint_as_float(lo), __uint_as_float(hi));
}
__device__ __forceinline__ float sigf(float x) {
    return __fdividef(1.f, 1.f + __expf(-x));
}
__device__ __forceinline__ float tanh_fast(float x) {
    return __fdividef(2.f, 1.f + __expf(-2.f * x)) - 1.f;
}
__device__ __forceinline__ unsigned to_tf32(float f) {
    unsigned r;
    asm("cvt.rna.tf32.f32 %0, %1;" : "=r"(r) : "f"(f));
    return r;
}
__device__ __forceinline__ void mma_tf32(float d[4],
                                         unsigned a0, unsigned a1, unsigned a2, unsigned a3,
                                         unsigned b0, unsigned b1) {
    asm("mma.sync.aligned.m16n8k8.row.col.f32.tf32.tf32.f32 "
        "{%0,%1,%2,%3}, {%4,%5,%6,%7}, {%8,%9}, {%0,%1,%2,%3};"
        : "+f"(d[0]), "+f"(d[1]), "+f"(d[2]), "+f"(d[3])
        : "r"(a0), "r"(a1), "r"(a2), "r"(a3), "r"(b0), "r"(b1));
}

// ============================================================
// tf32 tensor-core GEMM: C[M,N] = act(A[M,K] @ W[N,K]^T + b1 + b2)
// BM=128 BN=64 BK=32, 256 thr = 8 warps (4M x 2N), warp tile 32x32.
// smem layout [ks][row][perm(k%8)] with perm(k)=(k&3)*2+(k>>2) so
// fragment pairs (a0,a2),(a1,a3),(b0,b1) are contiguous LDS.64.
// Inputs rounded to tf32 at staging (cvt.rna), fp32 accumulate.
// GATHER=1: A row r -> input[b][t][:], r = t*BATCH + b.
// grid: x = n-blocks, y = m-blocks.
// ============================================================
template<int GATHER, int ACT>
__global__ __launch_bounds__(256)
void gemm_tf32(const float* __restrict__ A, const float* __restrict__ W,
               const float* __restrict__ bias1, const float* __restrict__ bias2,
               float* __restrict__ C, int M, int N, int K)
{
    constexpr int BM = 128, BN = 64, BK = 32;
    __shared__ __align__(16) float As[4][BM][8];
    __shared__ __align__(16) float Bs[4][BN][8];

    const int tid  = threadIdx.x;
    const int wid  = tid >> 5;
    const int lane = tid & 31;
    const int gid  = lane >> 2;   // 0..7
    const int tig  = lane & 3;    // 0..3
    const int wM   = wid & 3;     // 0..3
    const int wN   = wid >> 2;    // 0..1

    const int mbase = blockIdx.y * BM;
    const int nbase = blockIdx.x * BN;

    // staging coords: thread owns k-column = lane, rows wid + 8*i
    const int sk  = lane;                      // k within tile (0..31)
    const int sks = sk >> 3;                   // slab
    const int spp = (sk & 3) * 2 + ((sk >> 2) & 1);  // perm within slab

    // A row global offsets (gather fused)
    long a_off[16];
#pragma unroll
    for (int i = 0; i < 16; i++) {
        int arow = wid + 8 * i;
        int gr = mbase + arow;
        if (GATHER) {
            int b = gr & (BATCH - 1);
            int t = gr >> 8;
            a_off[i] = (long)(b * T_STEPS + t) * K;
        } else {
            a_off[i] = (long)gr * K;
        }
    }

    const int KT = (K + BK - 1) / BK;
    float a_ld[16], b_ld[8];

    // prefetch tile 0
    {
        int kg = sk;
        bool kin = (kg < K);
#pragma unroll
        for (int i = 0; i < 16; i++)
            a_ld[i] = kin ? A[a_off[i] + kg] : 0.f;
#pragma unroll
        for (int i = 0; i < 8; i++) {
            int n = nbase + wid + 8 * i;
            b_ld[i] = (kin && n < N) ? W[(long)n * K + kg] : 0.f;
        }
    }

    float d[2][4][4];
#pragma unroll
    for (int mt = 0; mt < 2; mt++)
#pragma unroll
        for (int nt = 0; nt < 4; nt++)
#pragma unroll
            for (int e = 0; e < 4; e++) d[mt][nt][e] = 0.f;

    for (int kt = 0; kt < KT; kt++) {
        // store staged tile (tf32-rounded)
#pragma unroll
        for (int i = 0; i < 16; i++)
            As[sks][wid + 8 * i][spp] = __uint_as_float(to_tf32(a_ld[i]));
#pragma unroll
        for (int i = 0; i < 8; i++)
            Bs[sks][wid + 8 * i][spp] = __uint_as_float(to_tf32(b_ld[i]));
        __syncthreads();

        // prefetch next tile
        if (kt + 1 < KT) {
            int kg = (kt + 1) * BK + sk;
            bool kin = (kg < K);
#pragma unroll
            for (int i = 0; i < 16; i++)
                a_ld[i] = kin ? A[a_off[i] + kg] : 0.f;
#pragma unroll
            for (int i = 0; i < 8; i++) {
                int n = nbase + wid + 8 * i;
                b_ld[i] = (kin && n < N) ? W[(long)n * K + kg] : 0.f;
            }
        }

        // compute: 4 k-steps of 8
#pragma unroll
        for (int ks = 0; ks < 4; ks++) {
            float2 aLo[2], aHi[2], bF[4];
#pragma unroll
            for (int mt = 0; mt < 2; mt++) {
                aLo[mt] = *(const float2*)&As[ks][wM * 32 + mt * 16 + gid][tig * 2];
                aHi[mt] = *(const float2*)&As[ks][wM * 32 + mt * 16 + gid + 8][tig * 2];
            }
#pragma unroll
            for (int nt = 0; nt < 4; nt++)
                bF[nt] = *(const float2*)&Bs[ks][wN * 32 + nt * 8 + gid][tig * 2];

#pragma unroll
            for (int mt = 0; mt < 2; mt++) {
                unsigned a0 = __float_as_uint(aLo[mt].x);
                unsigned a2 = __float_as_uint(aLo[mt].y);
                unsigned a1 = __float_as_uint(aHi[mt].x);
                unsigned a3 = __float_as_uint(aHi[mt].y);
#pragma unroll
                for (int nt = 0; nt < 4; nt++)
                    mma_tf32(d[mt][nt], a0, a1, a2, a3,
                             __float_as_uint(bF[nt].x), __float_as_uint(bF[nt].y));
            }
        }
        __syncthreads();
    }

    // epilogue: c0 (r,c) c1 (r,c+1) c2 (r+8,c) c3 (r+8,c+1)
#pragma unroll
    for (int nt = 0; nt < 4; nt++) {
        int n = nbase + wN * 32 + nt * 8 + tig * 2;
        if (n < N) {
            float bb0 = bias1[n]     + (bias2 ? bias2[n]     : 0.f);
            float bb1 = bias1[n + 1] + (bias2 ? bias2[n + 1] : 0.f);
#pragma unroll
            for (int mt = 0; mt < 2; mt++) {
                int r0 = mbase + wM * 32 + mt * 16 + gid;
                float v0 = d[mt][nt][0] + bb0;
                float v1 = d[mt][nt][1] + bb1;
                float v2 = d[mt][nt][2] + bb0;
                float v3 = d[mt][nt][3] + bb1;
                if (ACT) { v0 = tanh_fast(v0); v1 = tanh_fast(v1);
                           v2 = tanh_fast(v2); v3 = tanh_fast(v3); }
                *(float2*)&C[(long)r0 * N + n]       = make_float2(v0, v1);
                *(float2*)&C[(long)(r0 + 8) * N + n] = make_float2(v2, v3);
            }
        }
    }
}

// ============================================================
// LSTM recurrence (unchanged from round 2; fp32 throughout).
// 256 blocks x 1 batch, 256 threads; thread gc owns gate column gc.
// ============================================================
__global__ __launch_bounds__(256)
void lstm_rec_kernel(const float* __restrict__ xp, const float* __restrict__ whh,
                     const float* __restrict__ h0, const float* __restrict__ c0,
                     float* __restrict__ hs, float* __restrict__ hn, float* __restrict__ cn)
{
    __shared__ __align__(16) float h_s[HID];
    __shared__ float gate_s[G4];

    const int tid = threadIdx.x;
    const int b   = blockIdx.x;

    ull wd[32];
    const ulonglong2* wrow = (const ulonglong2*)(whh + (long)tid * HID);
#pragma unroll
    for (int k = 0; k < 16; k++) {
        ulonglong2 v = wrow[k];
        wd[2 * k]     = v.x;
        wd[2 * k + 1] = v.y;
    }

    float c_reg = 0.f;
    if (tid < HID) {
        h_s[tid] = h0[b * HID + tid];
        c_reg    = c0[b * HID + tid];
    }
    __syncthreads();

    const int gtype = tid >> 6;
    float pre = xp[(long)b * G4 + tid];

    for (int t = 0; t < T_STEPS; t++) {
        float cur = pre;
        if (t + 1 < T_STEPS)
            pre = xp[((long)(t + 1) * BATCH + b) * G4 + tid];

        ull a0 = 0ull, a1 = 0ull;
        const ulonglong2* hp = (const ulonglong2*)h_s;
#pragma unroll
        for (int k = 0; k < 16; k++) {
            ulonglong2 h4 = hp[k];
            FFMA2(a0, wd[2 * k],     h4.x);
            FFMA2(a1, wd[2 * k + 1], h4.y);
        }
        float2 f0 = unpk(a0), f1 = unpk(a1);
        float z = cur + ((f0.x + f0.y) + (f1.x + f1.y));

        float v = (gtype == 2) ? tanh_fast(z) : sigf(z);
        gate_s[tid] = v;
        __syncthreads();

        if (tid < HID) {
            float ig = gate_s[tid];
            float fg = gate_s[64 + tid];
            float gg = gate_s[128 + tid];
            float og = gate_s[192 + tid];
            c_reg = fg * c_reg + ig * gg;
            float h = og * tanh_fast(c_reg);
            h_s[tid] = h;
            hs[((long)t * BATCH + b) * HID + tid] = h;
        }
        __syncthreads();
    }

    if (tid < HID) {
        if (hn) hn[b * HID + tid] = h_s[tid];
        if (cn) cn[b * HID + tid] = c_reg;
    }
}

// ============================================================
extern "C" void kernel_launch(void* const* d_in, const int* in_sizes, int n_in,
                              void* d_out, int out_size)
{
    const float* input = (const float*)d_in[0];
    const float* h_0   = (const float*)d_in[1];
    const float* c_0   = (const float*)d_in[2];
    const float* wih[3] = {(const float*)d_in[3],  (const float*)d_in[7],  (const float*)d_in[11]};
    const float* whh[3] = {(const float*)d_in[4],  (const float*)d_in[8],  (const float*)d_in[12]};
    const float* bih[3] = {(const float*)d_in[5],  (const float*)d_in[9],  (const float*)d_in[13]};
    const float* bhh[3] = {(const float*)d_in[6],  (const float*)d_in[10], (const float*)d_in[14]};
    const float* w1 = (const float*)d_in[15];
    const float* b1 = (const float*)d_in[16];
    const float* w2 = (const float*)d_in[17];
    const float* b2 = (const float*)d_in[18];
    float* out = (float*)d_out;

    float *xp, *hsA, *hsB;
    cudaGetSymbolAddress((void**)&xp,  g_xp);
    cudaGetSymbolAddress((void**)&hsA, g_hsA);
    cudaGetSymbolAddress((void**)&hsB, g_hsB);

    float* hn = nullptr;
    float* cn = nullptr;
    const long out_main = (long)MROWS * DIN;
    if ((long)out_size >= out_main + 6L * BATCH * HID) {
        hn = out + out_main;
        cn = hn + 3 * BATCH * HID;
    }

    const dim3 thr(256);
    const dim3 gN256(G4 / 64,            MROWS / 128);   // (4, 1024)
    const dim3 gN64 (1,                  MROWS / 128);
    const dim3 gN300((DIN + 63) / 64,    MROWS / 128);   // (5, 1024)

    // ---- layer 0 ----
    gemm_tf32<1, 0><<<gN256, thr>>>(input, wih[0], bih[0], bhh[0], xp, MROWS, G4, DIN);
    lstm_rec_kernel<<<BATCH, thr>>>(xp, whh[0], h_0, c_0, hsA, hn, cn);
    // ---- layer 1 ----
    gemm_tf32<0, 0><<<gN256, thr>>>(hsA, wih[1], bih[1], bhh[1], xp, MROWS, G4, HID);
    lstm_rec_kernel<<<BATCH, thr>>>(xp, whh[1],
                                    h_0 + BATCH * HID, c_0 + BATCH * HID, hsB,
                                    hn ? hn + BATCH * HID : nullptr,
                                    cn ? cn + BATCH * HID : nullptr);
    // ---- layer 2 ----
    gemm_tf32<0, 0><<<gN256, thr>>>(hsB, wih[2], bih[2], bhh[2], xp, MROWS, G4, HID);
    lstm_rec_kernel<<<BATCH, thr>>>(xp, whh[2],
                                    h_0 + 2 * BATCH * HID, c_0 + 2 * BATCH * HID, hsA,
                                    hn ? hn + 2 * BATCH * HID : nullptr,
                                    cn ? cn + 2 * BATCH * HID : nullptr);
    // ---- MLP head ----
    gemm_tf32<0, 1><<<gN64,  thr>>>(hsA, w1, b1, nullptr, hsB, MROWS, HID, HID);
    gemm_tf32<0, 0><<<gN300, thr>>>(hsB, w2, b2, nullptr, out, MROWS, DIN, HID);
}

// round 10
// speedup vs baseline: 1.1777x; 1.1777x over previous
#include <cuda_runtime.h>

#define T_STEPS 512
#define BATCH   256
#define HID     64
#define DIN     300
#define G4      256
#define MROWS   (T_STEPS * BATCH)

typedef unsigned long long ull;

// ---- scratch (allocation-free: device globals) ----
__device__ float g_xp [(size_t)MROWS * G4];
__device__ float g_hsA[(size_t)MROWS * HID];
__device__ float g_hsB[(size_t)MROWS * HID];

#define FFMA2(acc, a, b) \
    asm("fma.rn.f32x2 %0, %1, %2, %0;" : "+l"(acc) : "l"(a), "l"(b))

__device__ __forceinline__ float2 unpk(ull v) {
    unsigned lo, hi;
    asm("mov.b64 {%0, %1}, %2;" : "=r"(lo), "=r"(hi) : "l"(v));
    return make_float2(__uint_as_float(lo), __uint_as_float(hi));
}
// hardware tanh: single MUFU op (sm_75+)
__device__ __forceinline__ float tanh_hw(float x) {
    float y;
    asm("tanh.approx.f32 %0, %1;" : "=f"(y) : "f"(x));
    return y;
}
// sigmoid(x) = 0.5*tanh(0.5x) + 0.5  (exact identity; 1 MUFU + 1 FMA)
__device__ __forceinline__ float sig_hw(float x) {
    return fmaf(0.5f, tanh_hw(0.5f * x), 0.5f);
}
__device__ __forceinline__ unsigned to_tf32(float f) {
    unsigned r;
    asm("cvt.rna.tf32.f32 %0, %1;" : "=r"(r) : "f"(f));
    return r;
}
__device__ __forceinline__ void mma_tf32(float d[4],
                                         unsigned a0, unsigned a1, unsigned a2, unsigned a3,
                                         unsigned b0, unsigned b1) {
    asm("mma.sync.aligned.m16n8k8.row.col.f32.tf32.tf32.f32 "
        "{%0,%1,%2,%3}, {%4,%5,%6,%7}, {%8,%9}, {%0,%1,%2,%3};"
        : "+f"(d[0]), "+f"(d[1]), "+f"(d[2]), "+f"(d[3])
        : "r"(a0), "r"(a1), "r"(a2), "r"(a3), "r"(b0), "r"(b1));
}

// perm(k%8) so fragment pairs (a0,a2),(a1,a3),(b0,b1) are contiguous LDS.64
__device__ __forceinline__ int kperm(int k) { return (k & 3) * 2 + ((k >> 2) & 1); }

// ============================================================
// tf32 GEMM, K=300 path: BM=128 BN=64 BK=32, double-buffered smem,
// ONE __syncthreads per k-tile. 256 thr = 8 warps (4M x 2N).
// GATHER=1: A row r -> input[b][t][:], r = t*BATCH + b.
// ============================================================
template<int GATHER, int ACT>
__global__ __launch_bounds__(256)
void gemm_db(const float* __restrict__ A, const float* __restrict__ W,
             const float* __restrict__ bias1, const float* __restrict__ bias2,
             float* __restrict__ C, int M, int N, int K)
{
    constexpr int BM = 128, BN = 64, BK = 32;
    __shared__ __align__(16) float As[2][4][BM][8];
    __shared__ __align__(16) float Bs[2][4][BN][8];

    const int tid  = threadIdx.x;
    const int wid  = tid >> 5;
    const int lane = tid & 31;
    const int gid  = lane >> 2;
    const int tig  = lane & 3;
    const int wM   = wid & 3;
    const int wN   = wid >> 2;

    const int mbase = blockIdx.y * BM;
    const int nbase = blockIdx.x * BN;

    const int sk  = lane;
    const int sks = sk >> 3;
    const int spp = kperm(sk);

    long a_off[16];
#pragma unroll
    for (int i = 0; i < 16; i++) {
        int gr = mbase + wid + 8 * i;
        if (GATHER) {
            int b = gr & (BATCH - 1);
            int t = gr >> 8;
            a_off[i] = (long)(b * T_STEPS + t) * K;
        } else {
            a_off[i] = (long)gr * K;
        }
    }

    const int KT = (K + BK - 1) / BK;
    float a_ld[16], b_ld[8];

    // prefetch + stage tile 0
    {
        bool kin = (sk < K);
#pragma unroll
        for (int i = 0; i < 16; i++)
            a_ld[i] = kin ? A[a_off[i] + sk] : 0.f;
#pragma unroll
        for (int i = 0; i < 8; i++) {
            int n = nbase + wid + 8 * i;
            b_ld[i] = (kin && n < N) ? W[(long)n * K + sk] : 0.f;
        }
#pragma unroll
        for (int i = 0; i < 16; i++)
            As[0][sks][wid + 8 * i][spp] = __uint_as_float(to_tf32(a_ld[i]));
#pragma unroll
        for (int i = 0; i < 8; i++)
            Bs[0][sks][wid + 8 * i][spp] = __uint_as_float(to_tf32(b_ld[i]));
    }
    __syncthreads();

    float d[2][4][4];
#pragma unroll
    for (int mt = 0; mt < 2; mt++)
#pragma unroll
        for (int nt = 0; nt < 4; nt++)
#pragma unroll
            for (int e = 0; e < 4; e++) d[mt][nt][e] = 0.f;

    for (int kt = 0; kt < KT; kt++) {
        const int cur = kt & 1;
        const int nxt = cur ^ 1;

        // prefetch next tile into regs (overlaps with compute below)
        if (kt + 1 < KT) {
            int kg = (kt + 1) * BK + sk;
            bool kin = (kg < K);
#pragma unroll
            for (int i = 0; i < 16; i++)
                a_ld[i] = kin ? A[a_off[i] + kg] : 0.f;
#pragma unroll
            for (int i = 0; i < 8; i++) {
                int n = nbase + wid + 8 * i;
                b_ld[i] = (kin && n < N) ? W[(long)n * K + kg] : 0.f;
            }
        }

        // compute current buffer
#pragma unroll
        for (int ks = 0; ks < 4; ks++) {
            float2 aLo[2], aHi[2], bF[4];
#pragma unroll
            for (int mt = 0; mt < 2; mt++) {
                aLo[mt] = *(const float2*)&As[cur][ks][wM * 32 + mt * 16 + gid][tig * 2];
                aHi[mt] = *(const float2*)&As[cur][ks][wM * 32 + mt * 16 + gid + 8][tig * 2];
            }
#pragma unroll
            for (int nt = 0; nt < 4; nt++)
                bF[nt] = *(const float2*)&Bs[cur][ks][wN * 32 + nt * 8 + gid][tig * 2];
#pragma unroll
            for (int mt = 0; mt < 2; mt++) {
                unsigned a0 = __float_as_uint(aLo[mt].x);
                unsigned a2 = __float_as_uint(aLo[mt].y);
                unsigned a1 = __float_as_uint(aHi[mt].x);
                unsigned a3 = __float_as_uint(aHi[mt].y);
#pragma unroll
                for (int nt = 0; nt < 4; nt++)
                    mma_tf32(d[mt][nt], a0, a1, a2, a3,
                             __float_as_uint(bF[nt].x), __float_as_uint(bF[nt].y));
            }
        }

        // stage next buffer, single barrier
        if (kt + 1 < KT) {
#pragma unroll
            for (int i = 0; i < 16; i++)
                As[nxt][sks][wid + 8 * i][spp] = __uint_as_float(to_tf32(a_ld[i]));
#pragma unroll
            for (int i = 0; i < 8; i++)
                Bs[nxt][sks][wid + 8 * i][spp] = __uint_as_float(to_tf32(b_ld[i]));
            __syncthreads();
        }
    }

    // epilogue
#pragma unroll
    for (int nt = 0; nt < 4; nt++) {
        int n = nbase + wN * 32 + nt * 8 + tig * 2;
        if (n < N) {
            float bb0 = bias1[n]     + (bias2 ? bias2[n]     : 0.f);
            float bb1 = bias1[n + 1] + (bias2 ? bias2[n + 1] : 0.f);
#pragma unroll
            for (int mt = 0; mt < 2; mt++) {
                int r0 = mbase + wM * 32 + mt * 16 + gid;
                float v0 = d[mt][nt][0] + bb0;
                float v1 = d[mt][nt][1] + bb1;
                float v2 = d[mt][nt][2] + bb0;
                float v3 = d[mt][nt][3] + bb1;
                if (ACT) { v0 = tanh_hw(v0); v1 = tanh_hw(v1);
                           v2 = tanh_hw(v2); v3 = tanh_hw(v3); }
                *(float2*)&C[(long)r0 * N + n]       = make_float2(v0, v1);
                *(float2*)&C[(long)(r0 + 8) * N + n] = make_float2(v2, v3);
            }
        }
    }
}

// ============================================================
// tf32 GEMM, K=64 single-tile path: BM=128 BN=64 BK=64.
// Entire K fits one staging pass -> exactly ONE __syncthreads.
// ============================================================
template<int ACT>
__global__ __launch_bounds__(256)
void gemm_k64(const float* __restrict__ A, const float* __restrict__ W,
              const float* __restrict__ bias1, const float* __restrict__ bias2,
              float* __restrict__ C, int M, int N, int K)
{
    constexpr int BM = 128, BN = 64;
    __shared__ __align__(16) float As[8][BM][8];   // 32 KB
    __shared__ __align__(16) float Bs[8][BN][8];   // 16 KB

    const int tid  = threadIdx.x;
    const int wid  = tid >> 5;
    const int lane = tid & 31;
    const int gid  = lane >> 2;
    const int tig  = lane & 3;
    const int wM   = wid & 3;
    const int wN   = wid >> 2;

    const int mbase = blockIdx.y * BM;
    const int nbase = blockIdx.x * BN;

    // stage: thread covers k-columns {lane, lane+32}
#pragma unroll
    for (int kc = 0; kc < 2; kc++) {
        const int kg  = lane + 32 * kc;
        const int sks = kg >> 3;
        const int spp = kperm(kg);
        const bool kin = (kg < K);
#pragma unroll
        for (int i = 0; i < 16; i++) {
            int r = mbase + wid + 8 * i;
            float v = kin ? A[(long)r * K + kg] : 0.f;
            As[sks][wid + 8 * i][spp] = __uint_as_float(to_tf32(v));
        }
#pragma unroll
        for (int i = 0; i < 8; i++) {
            int n = nbase + wid + 8 * i;
            float v = (kin && n < N) ? W[(long)n * K + kg] : 0.f;
            Bs[sks][wid + 8 * i][spp] = __uint_as_float(to_tf32(v));
        }
    }
    __syncthreads();

    float d[2][4][4];
#pragma unroll
    for (int mt = 0; mt < 2; mt++)
#pragma unroll
        for (int nt = 0; nt < 4; nt++)
#pragma unroll
            for (int e = 0; e < 4; e++) d[mt][nt][e] = 0.f;

#pragma unroll
    for (int ks = 0; ks < 8; ks++) {
        float2 aLo[2], aHi[2], bF[4];
#pragma unroll
        for (int mt = 0; mt < 2; mt++) {
            aLo[mt] = *(const float2*)&As[ks][wM * 32 + mt * 16 + gid][tig * 2];
            aHi[mt] = *(const float2*)&As[ks][wM * 32 + mt * 16 + gid + 8][tig * 2];
        }
#pragma unroll
        for (int nt = 0; nt < 4; nt++)
            bF[nt] = *(const float2*)&Bs[ks][wN * 32 + nt * 8 + gid][tig * 2];
#pragma unroll
        for (int mt = 0; mt < 2; mt++) {
            unsigned a0 = __float_as_uint(aLo[mt].x);
            unsigned a2 = __float_as_uint(aLo[mt].y);
            unsigned a1 = __float_as_uint(aHi[mt].x);
            unsigned a3 = __float_as_uint(aHi[mt].y);
#pragma unroll
            for (int nt = 0; nt < 4; nt++)
                mma_tf32(d[mt][nt], a0, a1, a2, a3,
                         __float_as_uint(bF[nt].x), __float_as_uint(bF[nt].y));
        }
    }

    // epilogue
#pragma unroll
    for (int nt = 0; nt < 4; nt++) {
        int n = nbase + wN * 32 + nt * 8 + tig * 2;
        if (n < N) {
            float bb0 = bias1[n]     + (bias2 ? bias2[n]     : 0.f);
            float bb1 = bias1[n + 1] + (bias2 ? bias2[n + 1] : 0.f);
#pragma unroll
            for (int mt = 0; mt < 2; mt++) {
                int r0 = mbase + wM * 32 + mt * 16 + gid;
                float v0 = d[mt][nt][0] + bb0;
                float v1 = d[mt][nt][1] + bb1;
                float v2 = d[mt][nt][2] + bb0;
                float v3 = d[mt][nt][3] + bb1;
                if (ACT) { v0 = tanh_hw(v0); v1 = tanh_hw(v1);
                           v2 = tanh_hw(v2); v3 = tanh_hw(v3); }
                *(float2*)&C[(long)r0 * N + n]       = make_float2(v0, v1);
                *(float2*)&C[(long)(r0 + 8) * N + n] = make_float2(v2, v3);
            }
        }
    }
}

// ============================================================
// LSTM recurrence: 256 blocks x 1 batch, 256 threads.
// Thread gc owns gate column gc; Whh row in regs (f32x2 pairs).
// Activations via single-MUFU tanh.approx (sigmoid by identity).
// ============================================================
__global__ __launch_bounds__(256)
void lstm_rec_kernel(const float* __restrict__ xp, const float* __restrict__ whh,
                     const float* __restrict__ h0, const float* __restrict__ c0,
                     float* __restrict__ hs, float* __restrict__ hn, float* __restrict__ cn)
{
    __shared__ __align__(16) float h_s[HID];
    __shared__ float gate_s[G4];

    const int tid = threadIdx.x;
    const int b   = blockIdx.x;

    ull wd[32];
    const ulonglong2* wrow = (const ulonglong2*)(whh + (long)tid * HID);
#pragma unroll
    for (int k = 0; k < 16; k++) {
        ulonglong2 v = wrow[k];
        wd[2 * k]     = v.x;
        wd[2 * k + 1] = v.y;
    }

    float c_reg = 0.f;
    if (tid < HID) {
        h_s[tid] = h0[b * HID + tid];
        c_reg    = c0[b * HID + tid];
    }
    __syncthreads();

    const int gtype = tid >> 6;
    float pre = xp[(long)b * G4 + tid];

    for (int t = 0; t < T_STEPS; t++) {
        float cur = pre;
        if (t + 1 < T_STEPS)
            pre = xp[((long)(t + 1) * BATCH + b) * G4 + tid];

        ull a0 = 0ull, a1 = 0ull;
        const ulonglong2* hp = (const ulonglong2*)h_s;
#pragma unroll
        for (int k = 0; k < 16; k++) {
            ulonglong2 h4 = hp[k];
            FFMA2(a0, wd[2 * k],     h4.x);
            FFMA2(a1, wd[2 * k + 1], h4.y);
        }
        float2 f0 = unpk(a0), f1 = unpk(a1);
        float z = cur + ((f0.x + f0.y) + (f1.x + f1.y));

        float v = (gtype == 2) ? tanh_hw(z) : sig_hw(z);
        gate_s[tid] = v;
        __syncthreads();

        if (tid < HID) {
            float ig = gate_s[tid];
            float fg = gate_s[64 + tid];
            float gg = gate_s[128 + tid];
            float og = gate_s[192 + tid];
            c_reg = fg * c_reg + ig * gg;
            float h = og * tanh_hw(c_reg);
            h_s[tid] = h;
            hs[((long)t * BATCH + b) * HID + tid] = h;
        }
        __syncthreads();
    }

    if (tid < HID) {
        if (hn) hn[b * HID + tid] = h_s[tid];
        if (cn) cn[b * HID + tid] = c_reg;
    }
}

// ============================================================
extern "C" void kernel_launch(void* const* d_in, const int* in_sizes, int n_in,
                              void* d_out, int out_size)
{
    const float* input = (const float*)d_in[0];
    const float* h_0   = (const float*)d_in[1];
    const float* c_0   = (const float*)d_in[2];
    const float* wih[3] = {(const float*)d_in[3],  (const float*)d_in[7],  (const float*)d_in[11]};
    const float* whh[3] = {(const float*)d_in[4],  (const float*)d_in[8],  (const float*)d_in[12]};
    const float* bih[3] = {(const float*)d_in[5],  (const float*)d_in[9],  (const float*)d_in[13]};
    const float* bhh[3] = {(const float*)d_in[6],  (const float*)d_in[10], (const float*)d_in[14]};
    const float* w1 = (const float*)d_in[15];
    const float* b1 = (const float*)d_in[16];
    const float* w2 = (const float*)d_in[17];
    const float* b2 = (const float*)d_in[18];
    float* out = (float*)d_out;

    float *xp, *hsA, *hsB;
    cudaGetSymbolAddress((void**)&xp,  g_xp);
    cudaGetSymbolAddress((void**)&hsA, g_hsA);
    cudaGetSymbolAddress((void**)&hsB, g_hsB);

    float* hn = nullptr;
    float* cn = nullptr;
    const long out_main = (long)MROWS * DIN;
    if ((long)out_size >= out_main + 6L * BATCH * HID) {
        hn = out + out_main;
        cn = hn + 3 * BATCH * HID;
    }

    const dim3 thr(256);
    const dim3 gN256(G4 / 64,         MROWS / 128);   // (4, 1024)
    const dim3 gN64 (1,               MROWS / 128);
    const dim3 gN300((DIN + 63) / 64, MROWS / 128);   // (5, 1024)

    // ---- layer 0 (K=300, double-buffered) ----
    gemm_db<1, 0><<<gN256, thr>>>(input, wih[0], bih[0], bhh[0], xp, MROWS, G4, DIN);
    lstm_rec_kernel<<<BATCH, thr>>>(xp, whh[0], h_0, c_0, hsA, hn, cn);
    // ---- layer 1 (K=64, single-tile) ----
    gemm_k64<0><<<gN256, thr>>>(hsA, wih[1], bih[1], bhh[1], xp, MROWS, G4, HID);
    lstm_rec_kernel<<<BATCH, thr>>>(xp, whh[1],
                                    h_0 + BATCH * HID, c_0 + BATCH * HID, hsB,
                                    hn ? hn + BATCH * HID : nullptr,
                                    cn ? cn + BATCH * HID : nullptr);
    // ---- layer 2 (K=64, single-tile) ----
    gemm_k64<0><<<gN256, thr>>>(hsB, wih[2], bih[2], bhh[2], xp, MROWS, G4, HID);
    lstm_rec_kernel<<<BATCH, thr>>>(xp, whh[2],
                                    h_0 + 2 * BATCH * HID, c_0 + 2 * BATCH * HID, hsA,
                                    hn ? hn + 2 * BATCH * HID : nullptr,
                                    cn ? cn + 2 * BATCH * HID : nullptr);
    // ---- MLP head (both K=64, single-tile) ----
    gemm_k64<1><<<gN64,  thr>>>(hsA, w1, b1, nullptr, hsB, MROWS, HID, HID);
    gemm_k64<0><<<gN300, thr>>>(hsB, w2, b2, nullptr, out, MROWS, DIN, HID);
}